// round 7
// baseline (speedup 1.0000x reference)
#include <cuda_runtime.h>

// Problem constants
#define BB   64      // batch
#define L0   128     // input length
#define C0   16      // input channels
#define L1C  124     // len after block1
#define CH1  128     // channels after block1
#define CH2  1024    // channels after block2
#define L3C  116     // len after block3
#define CH3  8192    // channels after block3

#define NSLICE 16
#define LCHUNK 29
#define NLC 4                            // 4 x 29 = 116 exactly
#define ZB  4                            // batch groups: 8 pairs per block
#define CTILES 128                       // 8 channels per tile
#define FUSED_BLOCKS (CTILES * NLC * ZB) // 2048
#define SPAN 33                          // x2 l-span per block = LCHUNK + 4
#define SPAN_PAD 34                      // padded so each (bp,c) row = 272B (16B mult)

typedef unsigned long long ull;

// Scratch (device globals; no runtime allocation allowed)
__device__ ull   g_out1p[(BB / 2) * L1C * CH1]; // [bpair][l][c1], packed batches
__device__ float g_acc [NSLICE][BB * 2];        // sliced dense accumulators
__device__ unsigned g_count;                    // completed-block counter

// ---------------------------------------------------------------------------
// Packed f32x2 helpers (sm_103a FFMA2 — PTX-only)
__device__ __forceinline__ ull pack2(float lo, float hi) {
    ull d; asm("mov.b64 %0, {%1, %2};" : "=l"(d) : "f"(lo), "f"(hi));
    return d;
}
__device__ __forceinline__ void unpack2(ull d, float& lo, float& hi) {
    asm("mov.b64 {%0, %1}, %2;" : "=f"(lo), "=f"(hi) : "l"(d));
}
__device__ __forceinline__ ull dup2(float v) {
    ull d; asm("mov.b64 %0, {%1, %1};" : "=l"(d) : "f"(v));
    return d;
}
__device__ __forceinline__ ull fma2(ull a, ull b, ull c) {
    ull d; asm("fma.rn.f32x2 %0, %1, %2, %3;" : "=l"(d) : "l"(a), "l"(b), "l"(c));
    return d;
}
__device__ __forceinline__ ull relu2(ull x) {
    float lo, hi; unpack2(x, lo, hi);
    return pack2(fmaxf(lo, 0.f), fmaxf(hi, 0.f));
}

// ---------------------------------------------------------------------------
// Block1 (+ zero accumulators/counter). out1 packed by batch pair.
__global__ void block1_kernel(const float* __restrict__ state,
                              const float* __restrict__ k1w,
                              const float* __restrict__ b1) {
    int idx = blockIdx.x * blockDim.x + threadIdx.x;
    if (idx < NSLICE * BB * 2) ((float*)g_acc)[idx] = 0.f;
    if (idx == 0) g_count = 0u;
    if (idx >= BB * L1C * CH1) return;
    int o = idx & (CH1 - 1);
    int l = (idx >> 7) % L1C;
    int b = idx / (L1C * CH1);
    int c = o >> 3;
    const float* sp = state + (b * L0 + l) * C0 + c;
    float v = b1[o];
#pragma unroll
    for (int k = 0; k < 5; k++) v = fmaf(sp[k * C0], k1w[k * CH1 + o], v);
    ((float*)g_out1p)[((size_t)(((b >> 1) * L1C + l) * CH1 + o) << 1) + (b & 1)] =
        fmaxf(v, 0.f);
}

// ---------------------------------------------------------------------------
// Fill helper: CNT consecutive packed x2 points, contiguous lrel writes.
template <int CNT>
__device__ __forceinline__ void fill_seg(const ull* __restrict__ op,
                                         ull* __restrict__ dst,
                                         const ull w2p[5], ull bias2p) {
    ull w[5];
#pragma unroll
    for (int k = 0; k < 5; k++) w[k] = op[(size_t)k * CH1];
#pragma unroll
    for (int i = 0; i < CNT; i++) {
        ull v = bias2p;
#pragma unroll
        for (int k = 0; k < 5; k++) v = fma2(w[(i + k) % 5], w2p[k], v);
        dst[i] = relu2(v);
        if (i + 1 < CNT) w[i % 5] = op[(size_t)(i + 5) * CH1];
    }
}

// ---------------------------------------------------------------------------
// Process one l-point: conv3 (2 filters) + relu + dense contribution.
// xw window slots are modular; W quad = (f0c0,f0c1,f1c0,f1c1).
__device__ __forceinline__ void do_l(int i, const ull xw[6],
                                     const ull w3p[5][2], const ull bias3p[2],
                                     ull u0, ull u1, ull& accC0, ull& accC1) {
    ull v0 = bias3p[0], v1 = bias3p[1];
#pragma unroll
    for (int k = 0; k < 5; k++) {
        v0 = fma2(xw[(i + k) % 6], w3p[k][0], v0);
        v1 = fma2(xw[(i + k) % 6], w3p[k][1], v1);
    }
    v0 = relu2(v0);            // packed (b_even, b_odd) for filter f0
    v1 = relu2(v1);            // filter f1
    float f0c0, f0c1, f1c0, f1c1;
    unpack2(u0, f0c0, f0c1);
    unpack2(u1, f1c0, f1c1);
    accC0 = fma2(v0, dup2(f0c0), accC0);
    accC1 = fma2(v0, dup2(f0c1), accC1);
    accC0 = fma2(v1, dup2(f1c0), accC0);
    accC1 = fma2(v1, dup2(f1c1), accC1);
}

// ---------------------------------------------------------------------------
// Fused block2 + block3 + dense + (last block) finalize. 256 threads.
// Phase 1: 256 threads fill x2 tile [8 bp][8 c][33 l] (lrel-contiguous).
// Phase 2: warp = batch pair; lane = (cl 0..7 channel, fq 0..3 -> 2 filters).
// Double-step l loop: one LDS128 refill per 2 l, one LDG128 W per l.
__global__ void __launch_bounds__(256, 4)
fused23_kernel(const float* __restrict__ k2w, const float* __restrict__ b2,
               const float* __restrict__ k3w, const float* __restrict__ b3,
               const float* __restrict__ W,   const float* __restrict__ bd,
               float* __restrict__ out) {
    __shared__ ull x2s[8 * 8 * SPAN_PAD];   // [bp][c][lrel]  17.4 KB
    int t  = threadIdx.x;
    int ct = blockIdx.x;                 // c-tile == out1 channel c1
    int l0 = blockIdx.y * LCHUNK;
    int zb = blockIdx.z;

    // ---------------- Phase 1: fill ----------------
    {
        int fc  = t & 7;                 // channel in tile
        int fbp = (t >> 3) & 7;          // batch pair in group
        int q   = t >> 6;                // l-quarter: lens 9,8,8,8 @ 0,9,17,25
        int cF  = ct * 8 + fc;

        ull w2p[5];
#pragma unroll
        for (int k = 0; k < 5; k++) {
            float w = k2w[k * CH2 + cF]; w2p[k] = pack2(w, w);
        }
        float bv = b2[cF];
        ull bias2p = pack2(bv, bv);

        int lrel0 = (q == 0) ? 0 : (q * 8 + 1);
        const ull* op = g_out1p +
            ((size_t)(zb * 8 + fbp) * L1C + l0 + lrel0) * CH1 + ct;
        ull* dst = &x2s[(fbp * 8 + fc) * SPAN_PAD + lrel0];
        if (q == 0) fill_seg<9>(op, dst, w2p, bias2p);
        else        fill_seg<8>(op, dst, w2p, bias2p);
    }
    __syncthreads();

    // ---------------- Phase 2: conv3 + dense ----------------
    int cl = t & 7;                      // channel lane
    int fq = (t >> 3) & 3;               // filters fq*2, fq*2+1
    int wg = t >> 5;                     // warp == batch pair in group
    int c  = ct * 8 + cl;

    ull w3p[5][2];
#pragma unroll
    for (int k = 0; k < 5; k++)
#pragma unroll
        for (int j = 0; j < 2; j++) {
            float w = k3w[k * CH3 + c * 8 + fq * 2 + j];
            w3p[k][j] = pack2(w, w);
        }
    ull bias3p[2];
#pragma unroll
    for (int j = 0; j < 2; j++) {
        float bv = b3[c * 8 + fq * 2 + j];
        bias3p[j] = pack2(bv, bv);
    }

    const ulonglong2* xsv =
        (const ulonglong2*)&x2s[(wg * 8 + cl) * SPAN_PAD];
    // W quad (f0c0,f0c1,f1c0,f1c1) at ulonglong2 index l*4096 + c*4 + fq
    const ulonglong2* Wq2 =
        (const ulonglong2*)W + ((size_t)l0 * 4096 + c * 4 + fq);

    ull xw[6];
    {
        ulonglong2 a = xsv[0], b_ = xsv[1], e = xsv[2];
        xw[0] = a.x; xw[1] = a.y; xw[2] = b_.x;
        xw[3] = b_.y; xw[4] = e.x; xw[5] = e.y;
    }

    ull accC0 = 0, accC1 = 0;   // packed (b_even, b_odd) sums per dense col

    ulonglong2 u = Wq2[0];
#pragma unroll
    for (int s = 0; s < 14; s++) {
        int i = 2 * s;
        ulonglong2 un1 = Wq2[(size_t)(i + 1) * 4096];
        ulonglong2 rf  = xsv[(i + 6) >> 1];           // x2[i+6], x2[i+7]
        do_l(i, xw, w3p, bias3p, u.x, u.y, accC0, accC1);
        ulonglong2 un2 = Wq2[(size_t)(i + 2) * 4096];
        do_l(i + 1, xw, w3p, bias3p, un1.x, un1.y, accC0, accC1);
        xw[i % 6]       = rf.x;
        xw[(i + 1) % 6] = rf.y;
        u = un2;
    }
    do_l(28, xw, w3p, bias3p, u.x, u.y, accC0, accC1);  // final odd l

    // Warp reduction over 32 lanes (8 c x 4 fq)
    float se0, so0, se1, so1;
    unpack2(accC0, se0, so0);
    unpack2(accC1, se1, so1);
#pragma unroll
    for (int s = 16; s > 0; s >>= 1) {
        se0 += __shfl_xor_sync(0xFFFFFFFFu, se0, s);
        so0 += __shfl_xor_sync(0xFFFFFFFFu, so0, s);
        se1 += __shfl_xor_sync(0xFFFFFFFFu, se1, s);
        so1 += __shfl_xor_sync(0xFFFFFFFFu, so1, s);
    }
    if ((t & 31) == 0) {
        int sl = ct & (NSLICE - 1);
        int be = (zb * 8 + wg) * 2;      // even batch of this pair
        atomicAdd(&g_acc[sl][be * 2],     se0);
        atomicAdd(&g_acc[sl][be * 2 + 1], se1);
        atomicAdd(&g_acc[sl][be * 2 + 2], so0);
        atomicAdd(&g_acc[sl][be * 2 + 3], so1);
    }

    // Last block finalizes (threadfence reduction pattern)
    __shared__ bool s_last;
    __threadfence();
    __syncthreads();
    if (t == 0) s_last = (atomicAdd(&g_count, 1u) == FUSED_BLOCKS - 1u);
    __syncthreads();
    if (s_last && t < 128) {
        __threadfence();
        int i = t;  // 128 outputs
        volatile float* ga = (volatile float*)g_acc;
        float v = 0.f;
#pragma unroll
        for (int s = 0; s < NSLICE; s++) v += ga[s * BB * 2 + i];
        out[i] = tanhf(v + bd[i & 1]);
    }
}

// ---------------------------------------------------------------------------
extern "C" void kernel_launch(void* const* d_in, const int* in_sizes, int n_in,
                              void* d_out, int out_size) {
    const float* state = (const float*)d_in[0];
    const float* k1w   = (const float*)d_in[1];
    const float* b1    = (const float*)d_in[2];
    const float* k2w   = (const float*)d_in[3];
    const float* b2    = (const float*)d_in[4];
    const float* k3w   = (const float*)d_in[5];
    const float* b3    = (const float*)d_in[6];
    const float* W     = (const float*)d_in[7];
    const float* bd    = (const float*)d_in[8];
    float* out = (float*)d_out;

    block1_kernel<<<(BB * L1C * CH1 + 255) / 256, 256>>>(state, k1w, b1);
    fused23_kernel<<<dim3(CTILES, NLC, ZB), 256>>>(k2w, b2, k3w, b3, W, bd, out);
}

// round 8
// speedup vs baseline: 1.6557x; 1.6557x over previous
#include <cuda_runtime.h>

// Problem constants
#define BB   64      // batch
#define L0   128     // input length
#define C0   16      // input channels
#define L1C  124     // len after block1
#define CH1  128     // channels after block1
#define CH2  1024    // channels after block2
#define L3C  116     // len after block3
#define CH3  8192    // channels after block3

#define NSLICE 16
#define LCHUNK 29
#define NLC 4                            // 4 x 29 = 116 exactly
#define ZB  2                            // batch groups: 16 pairs per block
#define CTILES 128                       // 8 channels per tile
#define FUSED_BLOCKS (CTILES * NLC * ZB) // 1024
#define SPAN 33                          // x2 l-span per block = LCHUNK + 4
#define SPAN_PAD 34                      // row = 272B (16B multiple)

typedef unsigned long long ull;

// Scratch (device globals; no runtime allocation allowed)
__device__ ull   g_out1p[(BB / 2) * L1C * CH1]; // [bpair][l][c1], packed batches
__device__ float g_acc [NSLICE][BB * 2];        // sliced dense accumulators
__device__ unsigned g_count;                    // completed-block counter

// ---------------------------------------------------------------------------
// Packed f32x2 helpers (sm_103a FFMA2 — PTX-only)
__device__ __forceinline__ ull pack2(float lo, float hi) {
    ull d; asm("mov.b64 %0, {%1, %2};" : "=l"(d) : "f"(lo), "f"(hi));
    return d;
}
__device__ __forceinline__ void unpack2(ull d, float& lo, float& hi) {
    asm("mov.b64 {%0, %1}, %2;" : "=f"(lo), "=f"(hi) : "l"(d));
}
__device__ __forceinline__ ull dup2(float v) {
    ull d; asm("mov.b64 %0, {%1, %1};" : "=l"(d) : "f"(v));
    return d;
}
__device__ __forceinline__ ull fma2(ull a, ull b, ull c) {
    ull d; asm("fma.rn.f32x2 %0, %1, %2, %3;" : "=l"(d) : "l"(a), "l"(b), "l"(c));
    return d;
}
__device__ __forceinline__ ull relu2(ull x) {
    float lo, hi; unpack2(x, lo, hi);
    return pack2(fmaxf(lo, 0.f), fmaxf(hi, 0.f));
}

// ---------------------------------------------------------------------------
// Block1 (+ zero accumulators/counter). out1 packed by batch pair.
__global__ void block1_kernel(const float* __restrict__ state,
                              const float* __restrict__ k1w,
                              const float* __restrict__ b1) {
    int idx = blockIdx.x * blockDim.x + threadIdx.x;
    if (idx < NSLICE * BB * 2) ((float*)g_acc)[idx] = 0.f;
    if (idx == 0) g_count = 0u;
    if (idx >= BB * L1C * CH1) return;
    int o = idx & (CH1 - 1);
    int l = (idx >> 7) % L1C;
    int b = idx / (L1C * CH1);
    int c = o >> 3;
    const float* sp = state + (b * L0 + l) * C0 + c;
    float v = b1[o];
#pragma unroll
    for (int k = 0; k < 5; k++) v = fmaf(sp[k * C0], k1w[k * CH1 + o], v);
    ((float*)g_out1p)[((size_t)(((b >> 1) * L1C + l) * CH1 + o) << 1) + (b & 1)] =
        fmaxf(v, 0.f);
}

// ---------------------------------------------------------------------------
// Fill helper: CNT consecutive packed x2 points, contiguous lrel writes.
template <int CNT>
__device__ __forceinline__ void fill_seg(const ull* __restrict__ op,
                                         ull* __restrict__ dst,
                                         const ull w2p[5], ull bias2p) {
    ull w[5];
#pragma unroll
    for (int k = 0; k < 5; k++) w[k] = op[(size_t)k * CH1];
#pragma unroll
    for (int i = 0; i < CNT; i++) {
        ull v = bias2p;
#pragma unroll
        for (int k = 0; k < 5; k++) v = fma2(w[(i + k) % 5], w2p[k], v);
        dst[i] = relu2(v);
        if (i + 1 < CNT) w[i % 5] = op[(size_t)(i + 5) * CH1];
    }
}

// ---------------------------------------------------------------------------
// One l-point for 4 batch pairs. W scalars dup'd ONCE, shared by all pairs.
__device__ __forceinline__ void do_l4(int i, const ull xw[4][6],
                                      const ull w3p[5][2], const ull bias3p[2],
                                      ull u0, ull u1,
                                      ull accC0[4], ull accC1[4]) {
    float f0c0, f0c1, f1c0, f1c1;
    unpack2(u0, f0c0, f0c1);
    unpack2(u1, f1c0, f1c1);
    ull d00 = dup2(f0c0), d01 = dup2(f0c1);
    ull d10 = dup2(f1c0), d11 = dup2(f1c1);
#pragma unroll
    for (int p = 0; p < 4; p++) {
        ull v0 = bias3p[0], v1 = bias3p[1];
#pragma unroll
        for (int k = 0; k < 5; k++) {
            v0 = fma2(xw[p][(i + k) % 6], w3p[k][0], v0);
            v1 = fma2(xw[p][(i + k) % 6], w3p[k][1], v1);
        }
        v0 = relu2(v0);
        v1 = relu2(v1);
        accC0[p] = fma2(v0, d00, accC0[p]);
        accC1[p] = fma2(v0, d01, accC1[p]);
        accC0[p] = fma2(v1, d10, accC0[p]);
        accC1[p] = fma2(v1, d11, accC1[p]);
    }
}

// ---------------------------------------------------------------------------
// Fused block2 + block3 + dense + (last block) finalize. 128 threads.
// Phase 1: fill x2 tile [16 bp][8 c][33 l] (lrel-contiguous) — one (bp,c)
//   row per thread, fully unrolled.
// Phase 2: warp wg handles batch pairs wg*4..wg*4+3 (8 batches/thread);
//   lane = (cl 0..7 channel, fq 0..3 -> 2 filters). Double-step l loop:
//   4 LDS128 refills per 2 l, 1 LDG128 W quad per l shared across 4 pairs.
__global__ void __launch_bounds__(128, 4)
fused23_kernel(const float* __restrict__ k2w, const float* __restrict__ b2,
               const float* __restrict__ k3w, const float* __restrict__ b3,
               const float* __restrict__ W,   const float* __restrict__ bd,
               float* __restrict__ out) {
    __shared__ ull x2s[16 * 8 * SPAN_PAD];   // [bp][c][lrel]  34.8 KB
    int t  = threadIdx.x;
    int ct = blockIdx.x;                 // c-tile == out1 channel c1
    int l0 = blockIdx.y * LCHUNK;
    int zb = blockIdx.z;                 // 0/1 -> batch pairs zb*16..+15

    // ---------------- Phase 1: fill ----------------
    {
        int fc  = t & 7;                 // channel in tile
        int fbp = t >> 3;                // batch pair 0..15
        int cF  = ct * 8 + fc;

        ull w2p[5];
#pragma unroll
        for (int k = 0; k < 5; k++) {
            float w = k2w[k * CH2 + cF]; w2p[k] = pack2(w, w);
        }
        float bv = b2[cF];
        ull bias2p = pack2(bv, bv);

        const ull* op = g_out1p +
            ((size_t)(zb * 16 + fbp) * L1C + l0) * CH1 + ct;
        ull* dst = &x2s[(fbp * 8 + fc) * SPAN_PAD];
        fill_seg<SPAN>(op, dst, w2p, bias2p);
    }
    __syncthreads();

    // ---------------- Phase 2: conv3 + dense ----------------
    int cl = t & 7;                      // channel lane
    int fq = (t >> 3) & 3;               // filters fq*2, fq*2+1
    int wg = t >> 5;                     // warp -> pairs wg*4..wg*4+3
    int c  = ct * 8 + cl;

    ull w3p[5][2];
#pragma unroll
    for (int k = 0; k < 5; k++)
#pragma unroll
        for (int j = 0; j < 2; j++) {
            float w = k3w[k * CH3 + c * 8 + fq * 2 + j];
            w3p[k][j] = pack2(w, w);
        }
    ull bias3p[2];
#pragma unroll
    for (int j = 0; j < 2; j++) {
        float bv = b3[c * 8 + fq * 2 + j];
        bias3p[j] = pack2(bv, bv);
    }

    const ulonglong2* xsv[4];
#pragma unroll
    for (int p = 0; p < 4; p++)
        xsv[p] = (const ulonglong2*)&x2s[((wg * 4 + p) * 8 + cl) * SPAN_PAD];

    // W quad (f0c0,f0c1,f1c0,f1c1) at ulonglong2 index l*4096 + c*4 + fq
    const ulonglong2* Wq2 =
        (const ulonglong2*)W + ((size_t)l0 * 4096 + c * 4 + fq);

    ull xw[4][6];
#pragma unroll
    for (int p = 0; p < 4; p++) {
        ulonglong2 a = xsv[p][0], b_ = xsv[p][1], e = xsv[p][2];
        xw[p][0] = a.x; xw[p][1] = a.y; xw[p][2] = b_.x;
        xw[p][3] = b_.y; xw[p][4] = e.x; xw[p][5] = e.y;
    }

    ull accC0[4] = {}, accC1[4] = {};    // packed (b_even, b_odd) per pair

    ulonglong2 u = Wq2[0];
#pragma unroll
    for (int s = 0; s < 14; s++) {
        int i = 2 * s;
        ulonglong2 un1 = Wq2[(size_t)(i + 1) * 4096];
        ulonglong2 rf0 = xsv[0][(i + 6) >> 1];
        ulonglong2 rf1 = xsv[1][(i + 6) >> 1];
        do_l4(i, xw, w3p, bias3p, u.x, u.y, accC0, accC1);
        ulonglong2 un2 = Wq2[(size_t)(i + 2) * 4096];
        ulonglong2 rf2 = xsv[2][(i + 6) >> 1];
        ulonglong2 rf3 = xsv[3][(i + 6) >> 1];
        do_l4(i + 1, xw, w3p, bias3p, un1.x, un1.y, accC0, accC1);
        xw[0][i % 6] = rf0.x; xw[0][(i + 1) % 6] = rf0.y;
        xw[1][i % 6] = rf1.x; xw[1][(i + 1) % 6] = rf1.y;
        xw[2][i % 6] = rf2.x; xw[2][(i + 1) % 6] = rf2.y;
        xw[3][i % 6] = rf3.x; xw[3][(i + 1) % 6] = rf3.y;
        u = un2;
    }
    do_l4(28, xw, w3p, bias3p, u.x, u.y, accC0, accC1);  // final odd l

    // Warp reduction over 32 lanes (8 c x 4 fq) per pair / batch-half / col
    int sl = ct & (NSLICE - 1);
#pragma unroll
    for (int p = 0; p < 4; p++) {
        float se0, so0, se1, so1;
        unpack2(accC0[p], se0, so0);
        unpack2(accC1[p], se1, so1);
#pragma unroll
        for (int s = 16; s > 0; s >>= 1) {
            se0 += __shfl_xor_sync(0xFFFFFFFFu, se0, s);
            so0 += __shfl_xor_sync(0xFFFFFFFFu, so0, s);
            se1 += __shfl_xor_sync(0xFFFFFFFFu, se1, s);
            so1 += __shfl_xor_sync(0xFFFFFFFFu, so1, s);
        }
        if ((t & 31) == 0) {
            int be = (zb * 16 + wg * 4 + p) * 2;   // even batch of this pair
            atomicAdd(&g_acc[sl][be * 2],     se0);
            atomicAdd(&g_acc[sl][be * 2 + 1], se1);
            atomicAdd(&g_acc[sl][be * 2 + 2], so0);
            atomicAdd(&g_acc[sl][be * 2 + 3], so1);
        }
    }

    // Last block finalizes (threadfence reduction pattern)
    __shared__ bool s_last;
    __threadfence();
    __syncthreads();
    if (t == 0) s_last = (atomicAdd(&g_count, 1u) == FUSED_BLOCKS - 1u);
    __syncthreads();
    if (s_last) {
        __threadfence();
        int i = t;  // 128 threads == 128 outputs
        volatile float* ga = (volatile float*)g_acc;
        float v = 0.f;
#pragma unroll
        for (int s = 0; s < NSLICE; s++) v += ga[s * BB * 2 + i];
        out[i] = tanhf(v + bd[i & 1]);
    }
}

// ---------------------------------------------------------------------------
extern "C" void kernel_launch(void* const* d_in, const int* in_sizes, int n_in,
                              void* d_out, int out_size) {
    const float* state = (const float*)d_in[0];
    const float* k1w   = (const float*)d_in[1];
    const float* b1    = (const float*)d_in[2];
    const float* k2w   = (const float*)d_in[3];
    const float* b2    = (const float*)d_in[4];
    const float* k3w   = (const float*)d_in[5];
    const float* b3    = (const float*)d_in[6];
    const float* W     = (const float*)d_in[7];
    const float* bd    = (const float*)d_in[8];
    float* out = (float*)d_out;

    block1_kernel<<<(BB * L1C * CH1 + 255) / 256, 256>>>(state, k1w, b1);
    fused23_kernel<<<dim3(CTILES, NLC, ZB), 128>>>(k2w, b2, k3w, b3, W, bd, out);
}